// round 8
// baseline (speedup 1.0000x reference)
#include <cuda_runtime.h>
#include <cuda_bf16.h>
#include <cstdint>

// Problem shape (fixed by reference): B=64, S=512, D=512.
#define S_DIM 512
#define D_DIM 512
#define KCB 32           // bf16 K elements per pipeline stage
#define STR 20           // smem row stride in 4B words (16 data words + 4 pad) -> conflict-free
#define NEG_VAL (-1e9f)

// Scratch (device globals — no allocation allowed)
__device__ __nv_bfloat16 g_n1[64 * S_DIM * D_DIM];   // normalized bf16 copy of e1
__device__ __nv_bfloat16 g_n2[64 * S_DIM * D_DIM];   // normalized bf16 copy of e2
__device__ unsigned g_rmax[64 * S_DIM];
__device__ unsigned g_cmax[64 * S_DIM];

// ---------- order-preserving float <-> uint encoding for atomicMax ----------
__device__ __forceinline__ unsigned encf(float f) {
    unsigned u = __float_as_uint(f);
    return (u & 0x80000000u) ? ~u : (u | 0x80000000u);
}
__device__ __forceinline__ float decf(unsigned k) {
    unsigned u = (k & 0x80000000u) ? (k ^ 0x80000000u) : ~k;
    return __uint_as_float(u);
}

// ---------- cp.async helpers ----------
__device__ __forceinline__ void cp_async16(unsigned saddr, const void* g) {
    asm volatile("cp.async.cg.shared.global [%0], [%1], 16;\n" :: "r"(saddr), "l"(g));
}
__device__ __forceinline__ void cp_commit() {
    asm volatile("cp.async.commit_group;\n");
}
template <int N>
__device__ __forceinline__ void cp_wait() {
    asm volatile("cp.async.wait_group %0;\n" :: "n"(N));
}

// ldmatrix x4 (non-transposed, b16)
__device__ __forceinline__ void ldsm_x4(unsigned r[4], unsigned saddr) {
    asm volatile("ldmatrix.sync.aligned.m8n8.x4.shared.b16 {%0,%1,%2,%3}, [%4];\n"
        : "=r"(r[0]), "=r"(r[1]), "=r"(r[2]), "=r"(r[3]) : "r"(saddr));
}

// m16n8k16 bf16 MMA, fp32 accumulate
__device__ __forceinline__ void mma_bf16(float c[4], const unsigned a[4],
                                         unsigned b0, unsigned b1) {
    asm volatile(
        "mma.sync.aligned.m16n8k16.row.col.f32.bf16.bf16.f32 "
        "{%0,%1,%2,%3}, {%4,%5,%6,%7}, {%8,%9}, {%0,%1,%2,%3};\n"
        : "+f"(c[0]), "+f"(c[1]), "+f"(c[2]), "+f"(c[3])
        : "r"(a[0]), "r"(a[1]), "r"(a[2]), "r"(a[3]), "r"(b0), "r"(b1));
}

// =====================================================================
// Kernel 1: per-row inverse L2 norm, write normalized bf16 copy,
// and reset the global max buffers. One warp per token row.
// =====================================================================
__global__ void norm_conv_kernel(const float* __restrict__ e1,
                                 const float* __restrict__ e2, int BS) {
    int w = (blockIdx.x * blockDim.x + threadIdx.x) >> 5;
    int lane = threadIdx.x & 31;
    if (w >= 2 * BS) return;
    const bool first = (w < BS);
    const int row = first ? w : (w - BS);
    const float* src = (first ? e1 : e2) + (size_t)row * D_DIM;

    // lane handles 16 contiguous floats: cols [16*lane, 16*lane+16)
    const float4* p = (const float4*)(src + lane * 16);
    float4 v[4];
#pragma unroll
    for (int q = 0; q < 4; q++) v[q] = p[q];

    float s = 0.f;
#pragma unroll
    for (int q = 0; q < 4; q++)
        s += v[q].x * v[q].x + v[q].y * v[q].y + v[q].z * v[q].z + v[q].w * v[q].w;
#pragma unroll
    for (int o = 16; o; o >>= 1) s += __shfl_xor_sync(0xffffffffu, s, o);

    const float inv = 1.0f / fmaxf(sqrtf(s), 1e-8f);

    // convert 16 normalized floats -> 8 bf16x2 words -> 2 x 16B stores
    unsigned wds[8];
    const float* f = (const float*)v;
#pragma unroll
    for (int i = 0; i < 8; i++) {
        __nv_bfloat162 h = __floats2bfloat162_rn(f[2 * i] * inv, f[2 * i + 1] * inv);
        wds[i] = *(unsigned*)&h;
    }
    __nv_bfloat16* dstbase = first ? g_n1 : g_n2;
    uint4* dst = (uint4*)(dstbase + (size_t)row * D_DIM + lane * 16);
    dst[0] = make_uint4(wds[0], wds[1], wds[2], wds[3]);
    dst[1] = make_uint4(wds[4], wds[5], wds[6], wds[7]);

    if (lane == 0) {
        unsigned negk = encf(NEG_VAL);
        if (first) g_rmax[row] = negk;
        else       g_cmax[row] = negk;
    }
}

// =====================================================================
// Kernel 2: per-batch bf16 GEMM (cosine sims directly — data already
// normalized) fused with masked row/col max.
// Grid: (jtile=4, itile=4, batch=B). CTA tile 128x128, 8 warps (2x4) of 64x32.
// Fragment loads via ldmatrix.x4 (12 LDSM vs 48 LDS per chunk).
// =====================================================================
__global__ __launch_bounds__(256, 2)
void gemm_max_kernel(const int* __restrict__ m1, const int* __restrict__ m2) {
    __shared__ unsigned As[2][128 * STR];
    __shared__ unsigned Bs[2][128 * STR];

    const int b  = blockIdx.z;
    const int i0 = blockIdx.y * 128;
    const int j0 = blockIdx.x * 128;
    const int t = threadIdx.x, lane = t & 31, w = t >> 5;
    const int wm = w >> 2, wn = w & 3;           // warp grid 2 x 4

    const __nv_bfloat16* Ag = g_n1 + ((size_t)b * S_DIM + i0) * D_DIM;
    const __nv_bfloat16* Bg = g_n2 + ((size_t)b * S_DIM + j0) * D_DIM;

    const unsigned sA = (unsigned)__cvta_generic_to_shared(&As[0][0]);
    const unsigned sB = (unsigned)__cvta_generic_to_shared(&Bs[0][0]);
    const unsigned bufBytes = 128 * STR * 4;     // 10240

    // ldmatrix per-lane base addresses (byte offsets into a buffer):
    // A tile (fm): rows wm*64+fm*16+(lane&15), halves (lane>>4)*4 words.
    const int lmRow = lane & 15;
    const int lmHalf = (lane >> 4) * 4;          // word offset for k-half
    unsigned aAddr[4], bAddr[2];
#pragma unroll
    for (int fm = 0; fm < 4; fm++)
        aAddr[fm] = sA + (unsigned)(((wm * 64 + fm * 16 + lmRow) * STR + lmHalf) * 4);
#pragma unroll
    for (int g = 0; g < 2; g++)
        bAddr[g] = sB + (unsigned)(((wn * 32 + g * 16 + lmRow) * STR + lmHalf) * 4);

    float acc[4][4][4];
#pragma unroll
    for (int a = 0; a < 4; a++)
#pragma unroll
        for (int bb = 0; bb < 4; bb++)
#pragma unroll
            for (int c = 0; c < 4; c++) acc[a][bb][c] = 0.f;

    // per chunk per matrix: 128 rows x 32 bf16 = 8KB = 512 granules of 16B;
    // thread handles granules t and t+256: row = g>>2, sub = g&3.
    auto load_chunk = [&](int c, int buf) {
        unsigned base = (unsigned)buf * bufBytes;
#pragma unroll
        for (int q = 0; q < 2; q++) {
            int g = t + 256 * q;
            int row = g >> 2, sub = g & 3;
            unsigned so = base + (unsigned)(row * STR + sub * 4) * 4u;
            size_t go = (size_t)row * (D_DIM * 2) + (size_t)c * (KCB * 2) + sub * 16;
            cp_async16(sA + so, (const char*)Ag + go);
            cp_async16(sB + so, (const char*)Bg + go);
        }
    };

    const int NC = D_DIM / KCB;  // 16
    load_chunk(0, 0);
    cp_commit();

    for (int c = 0; c < NC; c++) {
        if (c + 1 < NC) {
            load_chunk(c + 1, (c + 1) & 1);
            cp_commit();
            cp_wait<1>();
        } else {
            cp_wait<0>();
        }
        __syncthreads();

        const unsigned bufOff = (unsigned)(c & 1) * bufBytes;
#pragma unroll
        for (int s = 0; s < 2; s++) {            // two k16 steps per KCB=32
            const unsigned kOff = bufOff + (unsigned)(s * 8 * 4);
            unsigned afr[4][4], bfr[2][4];
#pragma unroll
            for (int fm = 0; fm < 4; fm++) ldsm_x4(afr[fm], aAddr[fm] + kOff);
#pragma unroll
            for (int g = 0; g < 2; g++) ldsm_x4(bfr[g], bAddr[g] + kOff);
            // bfr[g] = {n0-7:k0-7, n8-15:k0-7, n0-7:k8-15, n8-15:k8-15}
#pragma unroll
            for (int fm = 0; fm < 4; fm++) {
#pragma unroll
                for (int fn = 0; fn < 4; fn++) {
                    const int g = fn >> 1, h = fn & 1;
                    mma_bf16(acc[fm][fn], afr[fm], bfr[g][h], bfr[g][h + 2]);
                }
            }
        }
        __syncthreads();
    }

    // ---------------- epilogue: mask, row/col max (values are cosines) ----------------
    int mr[8], mc[8];
#pragma unroll
    for (int fm = 0; fm < 4; fm++)
#pragma unroll
        for (int h = 0; h < 2; h++) {
            int gi = i0 + wm * 64 + fm * 16 + h * 8 + (lane >> 2);
            mr[fm * 2 + h] = m1[b * S_DIM + gi];
        }
#pragma unroll
    for (int fn = 0; fn < 4; fn++)
#pragma unroll
        for (int h = 0; h < 2; h++) {
            int gj = j0 + wn * 32 + fn * 8 + (lane & 3) * 2 + h;
            mc[fn * 2 + h] = m2[b * S_DIM + gj];
        }

    float rmax[8], cmax[8];
#pragma unroll
    for (int q = 0; q < 8; q++) { rmax[q] = NEG_VAL; cmax[q] = NEG_VAL; }

#pragma unroll
    for (int fm = 0; fm < 4; fm++) {
#pragma unroll
        for (int fn = 0; fn < 4; fn++) {
            const float* cc = acc[fm][fn];
            int ri0 = fm * 2, ri1 = fm * 2 + 1;
            int ci0 = fn * 2, ci1 = fn * 2 + 1;
            if (mc[ci0]) { rmax[ri0] = fmaxf(rmax[ri0], cc[0]); rmax[ri1] = fmaxf(rmax[ri1], cc[2]); }
            if (mc[ci1]) { rmax[ri0] = fmaxf(rmax[ri0], cc[1]); rmax[ri1] = fmaxf(rmax[ri1], cc[3]); }
            if (mr[ri0]) { cmax[ci0] = fmaxf(cmax[ci0], cc[0]); cmax[ci1] = fmaxf(cmax[ci1], cc[1]); }
            if (mr[ri1]) { cmax[ci0] = fmaxf(cmax[ci0], cc[2]); cmax[ci1] = fmaxf(cmax[ci1], cc[3]); }
        }
    }

    // Row maxima: reduce across the 4 lanes of a row-group (same lane>>2).
#pragma unroll
    for (int o = 1; o < 4; o <<= 1)
#pragma unroll
        for (int q = 0; q < 8; q++)
            rmax[q] = fmaxf(rmax[q], __shfl_xor_sync(0xffffffffu, rmax[q], o));
    if ((lane & 3) == 0) {
#pragma unroll
        for (int q = 0; q < 8; q++) {
            int gi = i0 + wm * 64 + (q >> 1) * 16 + (q & 1) * 8 + (lane >> 2);
            atomicMax(&g_rmax[b * S_DIM + gi], encf(rmax[q]));
        }
    }
    // Col maxima: reduce across the 8 lanes sharing lane&3.
#pragma unroll
    for (int o = 4; o < 32; o <<= 1)
#pragma unroll
        for (int q = 0; q < 8; q++)
            cmax[q] = fmaxf(cmax[q], __shfl_xor_sync(0xffffffffu, cmax[q], o));
    if (lane < 4) {
#pragma unroll
        for (int q = 0; q < 8; q++) {
            int gj = j0 + wn * 32 + (q >> 1) * 8 + (lane & 3) * 2 + (q & 1);
            atomicMax(&g_cmax[b * S_DIM + gj], encf(cmax[q]));
        }
    }
}

// =====================================================================
// Kernel 3: final masked sums -> out[b]
// =====================================================================
__global__ void finalize_kernel(const int* __restrict__ m1, const int* __restrict__ m2,
                                float* __restrict__ out) {
    const int b = blockIdx.x, t = threadIdx.x;   // 512 threads
    const int idx = b * S_DIM + t;
    float v = 0.f, cnt = 0.f;
    if (m1[idx]) { v += decf(g_rmax[idx]); cnt += 1.f; }
    if (m2[idx]) { v += decf(g_cmax[idx]); cnt += 1.f; }
#pragma unroll
    for (int o = 16; o; o >>= 1) {
        v   += __shfl_xor_sync(0xffffffffu, v, o);
        cnt += __shfl_xor_sync(0xffffffffu, cnt, o);
    }
    __shared__ float sv[16], scn[16];
    int w = t >> 5, lane = t & 31;
    if (lane == 0) { sv[w] = v; scn[w] = cnt; }
    __syncthreads();
    if (w == 0) {
        float vv = (lane < 16) ? sv[lane] : 0.f;
        float cc = (lane < 16) ? scn[lane] : 0.f;
#pragma unroll
        for (int o = 8; o; o >>= 1) {
            vv += __shfl_xor_sync(0xffffffffu, vv, o);
            cc += __shfl_xor_sync(0xffffffffu, cc, o);
        }
        if (lane == 0) out[b] = vv / cc;
    }
}

extern "C" void kernel_launch(void* const* d_in, const int* in_sizes, int n_in,
                              void* d_out, int out_size) {
    const float* e1 = (const float*)d_in[0];
    const float* e2 = (const float*)d_in[1];
    const int*   m1 = (const int*)d_in[2];
    const int*   m2 = (const int*)d_in[3];
    const int B  = in_sizes[0] / (S_DIM * D_DIM);   // 64
    const int BS = B * S_DIM;

    norm_conv_kernel<<<(2 * BS + 7) / 8, 256>>>(e1, e2, BS);
    dim3 grid(S_DIM / 128, S_DIM / 128, B);          // (4, 4, 64)
    gemm_max_kernel<<<grid, 256>>>(m1, m2);
    finalize_kernel<<<B, S_DIM>>>(m1, m2, (float*)d_out);
}

// round 12
// speedup vs baseline: 1.5072x; 1.5072x over previous
#include <cuda_runtime.h>
#include <cuda_bf16.h>
#include <cstdint>

// Problem shape (fixed by reference): B=64, S=512, D=512.
#define S_DIM 512
#define D_DIM 512
#define KCB 32           // bf16 K elements per pipeline stage
#define STR 20           // smem row stride in 4B words (16 data words + 4 pad) -> conflict-free
#define NEG_VAL (-1e9f)

// Scratch (device globals — no allocation allowed). Zero-initialized at load;
// rows never written (invalid tokens) read back as 0.0 bf16 -> finite, masked out.
__device__ __nv_bfloat16 g_n1[64 * S_DIM * D_DIM];   // normalized bf16 copy of e1
__device__ __nv_bfloat16 g_n2[64 * S_DIM * D_DIM];   // normalized bf16 copy of e2
__device__ unsigned g_rmax[64 * S_DIM];
__device__ unsigned g_cmax[64 * S_DIM];

// ---------- order-preserving float <-> uint encoding for atomicMax ----------
__device__ __forceinline__ unsigned encf(float f) {
    unsigned u = __float_as_uint(f);
    return (u & 0x80000000u) ? ~u : (u | 0x80000000u);
}
__device__ __forceinline__ float decf(unsigned k) {
    unsigned u = (k & 0x80000000u) ? (k ^ 0x80000000u) : ~k;
    return __uint_as_float(u);
}

// ---------- cp.async helpers ----------
__device__ __forceinline__ void cp_async16(unsigned saddr, const void* g) {
    asm volatile("cp.async.cg.shared.global [%0], [%1], 16;\n" :: "r"(saddr), "l"(g));
}
__device__ __forceinline__ void cp_commit() {
    asm volatile("cp.async.commit_group;\n");
}
template <int N>
__device__ __forceinline__ void cp_wait() {
    asm volatile("cp.async.wait_group %0;\n" :: "n"(N));
}

// ldmatrix x4 (non-transposed, b16)
__device__ __forceinline__ void ldsm_x4(unsigned r[4], unsigned saddr) {
    asm volatile("ldmatrix.sync.aligned.m8n8.x4.shared.b16 {%0,%1,%2,%3}, [%4];\n"
        : "=r"(r[0]), "=r"(r[1]), "=r"(r[2]), "=r"(r[3]) : "r"(saddr));
}

// m16n8k16 bf16 MMA, fp32 accumulate
__device__ __forceinline__ void mma_bf16(float c[4], const unsigned a[4],
                                         unsigned b0, unsigned b1) {
    asm volatile(
        "mma.sync.aligned.m16n8k16.row.col.f32.bf16.bf16.f32 "
        "{%0,%1,%2,%3}, {%4,%5,%6,%7}, {%8,%9}, {%0,%1,%2,%3};\n"
        : "+f"(c[0]), "+f"(c[1]), "+f"(c[2]), "+f"(c[3])
        : "r"(a[0]), "r"(a[1]), "r"(a[2]), "r"(a[3]), "r"(b0), "r"(b1));
}

// =====================================================================
// Kernel 1: per-row inverse L2 norm, write normalized bf16 copy,
// reset max buffers. One warp per row; INVALID ROWS SKIPPED (their data
// is never consumed unmasked; unwritten scratch reads as 0).
// =====================================================================
__global__ void norm_conv_kernel(const float* __restrict__ e1,
                                 const float* __restrict__ e2,
                                 const int* __restrict__ m1,
                                 const int* __restrict__ m2, int BS) {
    int w = (blockIdx.x * blockDim.x + threadIdx.x) >> 5;
    int lane = threadIdx.x & 31;
    if (w >= 2 * BS) return;
    const bool first = (w < BS);
    const int row = first ? w : (w - BS);

    const int valid = first ? m1[row] : m2[row];
    if (lane == 0) {
        unsigned negk = encf(NEG_VAL);
        if (first) g_rmax[row] = negk;
        else       g_cmax[row] = negk;
    }
    if (!valid) return;   // prefix mask: row unused by any un-masked consumer

    const float* src = (first ? e1 : e2) + (size_t)row * D_DIM;
    const float4* p = (const float4*)(src + lane * 16);
    float4 v[4];
#pragma unroll
    for (int q = 0; q < 4; q++) v[q] = p[q];

    float s = 0.f;
#pragma unroll
    for (int q = 0; q < 4; q++)
        s += v[q].x * v[q].x + v[q].y * v[q].y + v[q].z * v[q].z + v[q].w * v[q].w;
#pragma unroll
    for (int o = 16; o; o >>= 1) s += __shfl_xor_sync(0xffffffffu, s, o);

    const float inv = 1.0f / fmaxf(sqrtf(s), 1e-8f);

    unsigned wds[8];
    const float* f = (const float*)v;
#pragma unroll
    for (int i = 0; i < 8; i++) {
        __nv_bfloat162 h = __floats2bfloat162_rn(f[2 * i] * inv, f[2 * i + 1] * inv);
        wds[i] = *(unsigned*)&h;
    }
    __nv_bfloat16* dstbase = first ? g_n1 : g_n2;
    uint4* dst = (uint4*)(dstbase + (size_t)row * D_DIM + lane * 16);
    dst[0] = make_uint4(wds[0], wds[1], wds[2], wds[3]);
    dst[1] = make_uint4(wds[4], wds[5], wds[6], wds[7]);
}

// =====================================================================
// Kernel 2: per-batch bf16 GEMM fused with masked row/col max.
// Grid: (jtile=4, itile=4, batch=B). CTA tile 128x128, 8 warps of 64x32.
// PREFIX-MASK TILE SKIP: tile contributes only if its first row AND
// first col are valid (masks are contiguous prefixes).
// =====================================================================
__global__ __launch_bounds__(256, 2)
void gemm_max_kernel(const int* __restrict__ m1, const int* __restrict__ m2) {
    const int b  = blockIdx.z;
    const int i0 = blockIdx.y * 128;
    const int j0 = blockIdx.x * 128;

    // Early exit: with prefix masks, a tile whose first row/col is invalid
    // contains no (valid i, valid j) pair -> contributes nothing.
    if (m1[b * S_DIM + i0] == 0 || m2[b * S_DIM + j0] == 0) return;

    __shared__ unsigned As[2][128 * STR];
    __shared__ unsigned Bs[2][128 * STR];

    const int t = threadIdx.x, lane = t & 31, w = t >> 5;
    const int wm = w >> 2, wn = w & 3;           // warp grid 2 x 4

    const __nv_bfloat16* Ag = g_n1 + ((size_t)b * S_DIM + i0) * D_DIM;
    const __nv_bfloat16* Bg = g_n2 + ((size_t)b * S_DIM + j0) * D_DIM;

    const unsigned sA = (unsigned)__cvta_generic_to_shared(&As[0][0]);
    const unsigned sB = (unsigned)__cvta_generic_to_shared(&Bs[0][0]);
    const unsigned bufBytes = 128 * STR * 4;     // 10240

    const int lmRow = lane & 15;
    const int lmHalf = (lane >> 4) * 4;          // word offset for k-half
    unsigned aAddr[4], bAddr[2];
#pragma unroll
    for (int fm = 0; fm < 4; fm++)
        aAddr[fm] = sA + (unsigned)(((wm * 64 + fm * 16 + lmRow) * STR + lmHalf) * 4);
#pragma unroll
    for (int g = 0; g < 2; g++)
        bAddr[g] = sB + (unsigned)(((wn * 32 + g * 16 + lmRow) * STR + lmHalf) * 4);

    float acc[4][4][4];
#pragma unroll
    for (int a = 0; a < 4; a++)
#pragma unroll
        for (int bb = 0; bb < 4; bb++)
#pragma unroll
            for (int c = 0; c < 4; c++) acc[a][bb][c] = 0.f;

    auto load_chunk = [&](int c, int buf) {
        unsigned base = (unsigned)buf * bufBytes;
#pragma unroll
        for (int q = 0; q < 2; q++) {
            int g = t + 256 * q;
            int row = g >> 2, sub = g & 3;
            unsigned so = base + (unsigned)(row * STR + sub * 4) * 4u;
            size_t go = (size_t)row * (D_DIM * 2) + (size_t)c * (KCB * 2) + sub * 16;
            cp_async16(sA + so, (const char*)Ag + go);
            cp_async16(sB + so, (const char*)Bg + go);
        }
    };

    const int NC = D_DIM / KCB;  // 16
    load_chunk(0, 0);
    cp_commit();

    for (int c = 0; c < NC; c++) {
        if (c + 1 < NC) {
            load_chunk(c + 1, (c + 1) & 1);
            cp_commit();
            cp_wait<1>();
        } else {
            cp_wait<0>();
        }
        __syncthreads();

        const unsigned bufOff = (unsigned)(c & 1) * bufBytes;
#pragma unroll
        for (int s = 0; s < 2; s++) {            // two k16 steps per KCB=32
            const unsigned kOff = bufOff + (unsigned)(s * 8 * 4);
            unsigned afr[4][4], bfr[2][4];
#pragma unroll
            for (int fm = 0; fm < 4; fm++) ldsm_x4(afr[fm], aAddr[fm] + kOff);
#pragma unroll
            for (int g = 0; g < 2; g++) ldsm_x4(bfr[g], bAddr[g] + kOff);
#pragma unroll
            for (int fm = 0; fm < 4; fm++) {
#pragma unroll
                for (int fn = 0; fn < 4; fn++) {
                    const int g = fn >> 1, h = fn & 1;
                    mma_bf16(acc[fm][fn], afr[fm], bfr[g][h], bfr[g][h + 2]);
                }
            }
        }
        __syncthreads();
    }

    // ---------------- epilogue: mask, row/col max (values are cosines) ----------------
    int mr[8], mc[8];
#pragma unroll
    for (int fm = 0; fm < 4; fm++)
#pragma unroll
        for (int h = 0; h < 2; h++) {
            int gi = i0 + wm * 64 + fm * 16 + h * 8 + (lane >> 2);
            mr[fm * 2 + h] = m1[b * S_DIM + gi];
        }
#pragma unroll
    for (int fn = 0; fn < 4; fn++)
#pragma unroll
        for (int h = 0; h < 2; h++) {
            int gj = j0 + wn * 32 + fn * 8 + (lane & 3) * 2 + h;
            mc[fn * 2 + h] = m2[b * S_DIM + gj];
        }

    float rmax[8], cmax[8];
#pragma unroll
    for (int q = 0; q < 8; q++) { rmax[q] = NEG_VAL; cmax[q] = NEG_VAL; }

#pragma unroll
    for (int fm = 0; fm < 4; fm++) {
#pragma unroll
        for (int fn = 0; fn < 4; fn++) {
            const float* cc = acc[fm][fn];
            int ri0 = fm * 2, ri1 = fm * 2 + 1;
            int ci0 = fn * 2, ci1 = fn * 2 + 1;
            if (mc[ci0]) { rmax[ri0] = fmaxf(rmax[ri0], cc[0]); rmax[ri1] = fmaxf(rmax[ri1], cc[2]); }
            if (mc[ci1]) { rmax[ri0] = fmaxf(rmax[ri0], cc[1]); rmax[ri1] = fmaxf(rmax[ri1], cc[3]); }
            if (mr[ri0]) { cmax[ci0] = fmaxf(cmax[ci0], cc[0]); cmax[ci1] = fmaxf(cmax[ci1], cc[1]); }
            if (mr[ri1]) { cmax[ci0] = fmaxf(cmax[ci0], cc[2]); cmax[ci1] = fmaxf(cmax[ci1], cc[3]); }
        }
    }

    // Row maxima: reduce across the 4 lanes of a row-group (same lane>>2).
#pragma unroll
    for (int o = 1; o < 4; o <<= 1)
#pragma unroll
        for (int q = 0; q < 8; q++)
            rmax[q] = fmaxf(rmax[q], __shfl_xor_sync(0xffffffffu, rmax[q], o));
    if ((lane & 3) == 0) {
#pragma unroll
        for (int q = 0; q < 8; q++) {
            int gi = i0 + wm * 64 + (q >> 1) * 16 + (q & 1) * 8 + (lane >> 2);
            atomicMax(&g_rmax[b * S_DIM + gi], encf(rmax[q]));
        }
    }
    // Col maxima: reduce across the 8 lanes sharing lane&3.
#pragma unroll
    for (int o = 4; o < 32; o <<= 1)
#pragma unroll
        for (int q = 0; q < 8; q++)
            cmax[q] = fmaxf(cmax[q], __shfl_xor_sync(0xffffffffu, cmax[q], o));
    if (lane < 4) {
#pragma unroll
        for (int q = 0; q < 8; q++) {
            int gj = j0 + wn * 32 + (q >> 1) * 8 + (lane & 3) * 2 + (q & 1);
            atomicMax(&g_cmax[b * S_DIM + gj], encf(cmax[q]));
        }
    }
}

// =====================================================================
// Kernel 3: final masked sums -> out[b]
// =====================================================================
__global__ void finalize_kernel(const int* __restrict__ m1, const int* __restrict__ m2,
                                float* __restrict__ out) {
    const int b = blockIdx.x, t = threadIdx.x;   // 512 threads
    const int idx = b * S_DIM + t;
    float v = 0.f, cnt = 0.f;
    if (m1[idx]) { v += decf(g_rmax[idx]); cnt += 1.f; }
    if (m2[idx]) { v += decf(g_cmax[idx]); cnt += 1.f; }
#pragma unroll
    for (int o = 16; o; o >>= 1) {
        v   += __shfl_xor_sync(0xffffffffu, v, o);
        cnt += __shfl_xor_sync(0xffffffffu, cnt, o);
    }
    __shared__ float sv[16], scn[16];
    int w = t >> 5, lane = t & 31;
    if (lane == 0) { sv[w] = v; scn[w] = cnt; }
    __syncthreads();
    if (w == 0) {
        float vv = (lane < 16) ? sv[lane] : 0.f;
        float cc = (lane < 16) ? scn[lane] : 0.f;
#pragma unroll
        for (int o = 8; o; o >>= 1) {
            vv += __shfl_xor_sync(0xffffffffu, vv, o);
            cc += __shfl_xor_sync(0xffffffffu, cc, o);
        }
        if (lane == 0) out[b] = vv / cc;
    }
}

extern "C" void kernel_launch(void* const* d_in, const int* in_sizes, int n_in,
                              void* d_out, int out_size) {
    const float* e1 = (const float*)d_in[0];
    const float* e2 = (const float*)d_in[1];
    const int*   m1 = (const int*)d_in[2];
    const int*   m2 = (const int*)d_in[3];
    const int B  = in_sizes[0] / (S_DIM * D_DIM);   // 64
    const int BS = B * S_DIM;

    norm_conv_kernel<<<(2 * BS + 7) / 8, 256>>>(e1, e2, m1, m2, BS);
    dim3 grid(S_DIM / 128, S_DIM / 128, B);          // (4, 4, 64)
    gemm_max_kernel<<<grid, 256>>>(m1, m2);
    finalize_kernel<<<B, S_DIM>>>(m1, m2, (float*)d_out);
}